// round 2
// baseline (speedup 1.0000x reference)
#include <cuda_runtime.h>

// SinkhornScorer fused kernel for GB300 (sm_103a). One CTA per batch element.
// R2: 3 CTAs/SM (launch_bounds), 4-threads-per-row Sinkhorn with shfl reduce,
// K stored with row stride 68 + mod-4 column interleave (conflict-free u-phase),
// score folded into matching epilogue.

namespace {
constexpr int H   = 256;
constexpr int NN  = 64;     // NX == NY
constexpr int NP  = 65;     // with dustbin
constexpr int KP  = 68;     // K row stride (bank-conflict-free Sinkhorn)
constexpr float LOG128 = 4.852030263919617f;   // log(128)
constexpr float MU_IN  = 0.0078125f;           // 1/128
constexpr float MU_DB  = 0.5f;                 // 64/128

__device__ __forceinline__ float warp_sum(float v) {
#pragma unroll
    for (int o = 16; o; o >>= 1) v += __shfl_xor_sync(0xffffffffu, v, o);
    return v;
}
}  // namespace

__global__ void __launch_bounds__(256, 3) sinkhorn_fused_kernel(
    const float* __restrict__ x,      // (B, 64, 256)
    const float* __restrict__ y,      // (B, 64, 256)
    const float* __restrict__ gamma,  // (256,)
    const float* __restrict__ beta,   // (256,)
    const float* __restrict__ wdb,    // (256,1)
    const float* __restrict__ bdb,    // (1,)
    float* __restrict__ out_match,    // (B, 65, 65)
    float* __restrict__ out_score,    // (B,)
    int write_score)
{
    const int b    = blockIdx.x;
    const int t    = threadIdx.x;
    const int lane = t & 31;
    const int wid  = t >> 5;

    // Overlays: GEMM staging (xs 4096 | ys 4096 floats) then C(65x65) + K(65x68).
    __shared__ __align__(16) float sBuf[8768];
    __shared__ __align__(16) float sGw[256];   // gamma*w
    __shared__ float sScale[128];              // 1/||row||, x rows then y rows
    __shared__ float sAlpha[128];              // dustbin alphas
    __shared__ float sAv[NP], sBv[NP], sLa[NP], sLb[NP];
    __shared__ float sRed[16];
    __shared__ float sSgw, sSbw;

    // ---- constants: gw = gamma*w; S_gw = sum gw; S_bw = sum beta*w + b_db ----
    {
        float gwv = gamma[t] * wdb[t];
        float bwv = beta[t] * wdb[t];
        sGw[t] = gwv;
        gwv = warp_sum(gwv);
        bwv = warp_sum(bwv);
        if (lane == 0) { sRed[wid] = gwv; sRed[8 + wid] = bwv; }
    }
    __syncthreads();
    if (t == 0) {
        float a = 0.f, c = 0.f;
#pragma unroll
        for (int i = 0; i < 8; i++) { a += sRed[i]; c += sRed[8 + i]; }
        sSgw = a;
        sSbw = c + bdb[0];
    }
    __syncthreads();

    const float* xb = x + (size_t)b * NN * H;
    const float* yb = y + (size_t)b * NN * H;

    // ---- Phase A: per-row stats (one warp per row, 16 rows per warp) ----
    {
        const float4* gw4 = (const float4*)sGw;
        for (int rr = wid; rr < 128; rr += 8) {
            const float4* rp4 =
                (const float4*)((rr < 64) ? (xb + rr * H) : (yb + (rr - 64) * H));
            float s1 = 0.f, s2 = 0.f, s3 = 0.f;
#pragma unroll
            for (int q = 0; q < 2; q++) {
                float4 v = rp4[lane + 32 * q];
                float4 g = gw4[lane + 32 * q];
                s1 += (v.x + v.y) + (v.z + v.w);
                s2 += v.x * v.x + v.y * v.y + v.z * v.z + v.w * v.w;
                s3 += v.x * g.x + v.y * g.y + v.z * g.z + v.w * g.w;
            }
            s1 = warp_sum(s1);
            s2 = warp_sum(s2);
            s3 = warp_sum(s3);
            if (lane == 0) {
                sScale[rr] = 1.0f / fmaxf(sqrtf(s2), 1e-12f);
                float mu      = s1 * (1.0f / 256.0f);
                float var     = s2 * (1.0f / 256.0f) - mu * mu;
                float inv_std = rsqrtf(var + 1e-5f);
                sAlpha[rr] = tanhf(inv_std * (s3 - mu * sSgw) + sSbw);
            }
        }
    }
    __syncthreads();

    // ---- Phase B: GEMM  raw[i][j] = sum_k x[i][k]*y[j][k], 4x4 thread tiles ----
    float4* xs4 = (float4*)sBuf;           // [64 rows][16 float4], swizzled
    float4* ys4 = (float4*)(sBuf + 4096);
    const int ty = t >> 4;   // 0..15
    const int tx = t & 15;   // 0..15
    float acc[4][4] = {};

    const float4* xg = (const float4*)xb;   // 64 float4 per row
    const float4* yg = (const float4*)yb;

    for (int kc = 0; kc < 4; kc++) {
        __syncthreads();
#pragma unroll
        for (int q = 0; q < 4; q++) {
            int idx = t + 256 * q;        // 0..1023
            int row = idx >> 4;
            int c4  = idx & 15;
            int sw  = c4 ^ ((row >> 2) & 15);
            xs4[row * 16 + sw] = xg[row * 64 + kc * 16 + c4];
            ys4[row * 16 + sw] = yg[row * 64 + kc * 16 + c4];
        }
        __syncthreads();
#pragma unroll
        for (int k4 = 0; k4 < 16; k4++) {
            float4 xv[4];
#pragma unroll
            for (int ii = 0; ii < 4; ii++)
                xv[ii] = xs4[(ty * 4 + ii) * 16 + (k4 ^ ty)];
#pragma unroll
            for (int jj = 0; jj < 4; jj++) {
                float4 yv = ys4[(tx * 4 + jj) * 16 + (k4 ^ tx)];
#pragma unroll
                for (int ii = 0; ii < 4; ii++) {
                    float a = acc[ii][jj];
                    a = fmaf(xv[ii].x, yv.x, a);
                    a = fmaf(xv[ii].y, yv.y, a);
                    a = fmaf(xv[ii].z, yv.z, a);
                    a = fmaf(xv[ii].w, yv.w, a);
                    acc[ii][jj] = a;
                }
            }
        }
    }
    __syncthreads();   // staging reads done; safe to overlay C/K

    // ---- Phase C: C = 10*cos (stride 65) and K = exp(C) (stride 68) ----
    float* C = sBuf;          // 65*65 = 4225 floats
    float* K = sBuf + 4288;   // 65*68 = 4420 floats
#pragma unroll
    for (int ii = 0; ii < 4; ii++) {
#pragma unroll
        for (int jj = 0; jj < 4; jj++) {
            int i = ty * 4 + ii, j = tx * 4 + jj;
            float c = acc[ii][jj] * sScale[i] * sScale[64 + j] * 10.0f;
            C[i * NP + j] = c;
            K[i * KP + j] = __expf(c);
        }
    }
    if (t < 64) {
        float cx = 10.0f * sAlpha[t];          // alpha_x dustbin column
        C[t * NP + 64] = cx;  K[t * KP + 64] = __expf(cx);
        float cy = 10.0f * sAlpha[64 + t];     // alpha_y dustbin row
        C[64 * NP + t] = cy;  K[64 * KP + t] = __expf(cy);
    }
    if (t == 0) { C[64 * NP + 64] = -1000.0f; K[64 * KP + 64] = 0.0f; }
    if (t < NP) sBv[t] = 1.0f;                 // v = 0  ->  b = 1
    __syncthreads();

    // ---- Phase D: Sinkhorn, linear domain. 4 threads per row/col. ----
    const int r = t >> 2;    // 0..63
    const int q = t & 3;     // column-quarter via mod-4 interleave
    for (int it = 0; it < 20; it++) {
        // u-phase: row sums of K * b
        {
            const float* Kr = K + r * KP;
            float s0 = 0.f, s1 = 0.f;
#pragma unroll
            for (int j4 = 0; j4 < 16; j4 += 2) {
                s0 = fmaf(Kr[4 * j4 + q],     sBv[4 * j4 + q],     s0);
                s1 = fmaf(Kr[4 * j4 + 4 + q], sBv[4 * j4 + 4 + q], s1);
            }
            float s = s0 + s1;
            if (q == 0) s = fmaf(Kr[64], sBv[64], s);
            s += __shfl_xor_sync(0xffffffffu, s, 1);
            s += __shfl_xor_sync(0xffffffffu, s, 2);
            // row 64 (dustbin): warp 0, lanes 0..15, 4 cols each (col64 is 0)
            if (wid == 0) {
                float s64 = 0.f;
                if (lane < 16) {
                    const float* K64 = K + 64 * KP + 4 * lane;
                    const float* bv  = sBv + 4 * lane;
                    s64 = fmaf(K64[0], bv[0], fmaf(K64[1], bv[1],
                          fmaf(K64[2], bv[2], K64[3] * bv[3])));
                }
                s64 += __shfl_xor_sync(0xffffffffu, s64, 8);
                s64 += __shfl_xor_sync(0xffffffffu, s64, 4);
                s64 += __shfl_xor_sync(0xffffffffu, s64, 2);
                s64 += __shfl_xor_sync(0xffffffffu, s64, 1);
                if (lane == 0) sAv[64] = MU_DB / s64;
            }
            if (q == 0) sAv[r] = MU_IN / s;
        }
        __syncthreads();
        // v-phase: column sums of K^T * a
        {
            float s0 = 0.f, s1 = 0.f;
#pragma unroll
            for (int i4 = 0; i4 < 16; i4 += 2) {
                s0 = fmaf(K[(4 * i4 + q) * KP + r],     sAv[4 * i4 + q],     s0);
                s1 = fmaf(K[(4 * i4 + 4 + q) * KP + r], sAv[4 * i4 + 4 + q], s1);
            }
            float s = s0 + s1;
            if (q == 0) s = fmaf(K[64 * KP + r], sAv[64], s);
            s += __shfl_xor_sync(0xffffffffu, s, 1);
            s += __shfl_xor_sync(0xffffffffu, s, 2);
            if (wid == 0) {
                float s64 = 0.f;
                if (lane < 16) {
                    int i0 = 4 * lane;
                    s64 = fmaf(K[(i0 + 0) * KP + 64], sAv[i0 + 0],
                          fmaf(K[(i0 + 1) * KP + 64], sAv[i0 + 1],
                          fmaf(K[(i0 + 2) * KP + 64], sAv[i0 + 2],
                               K[(i0 + 3) * KP + 64] * sAv[i0 + 3])));
                }
                s64 += __shfl_xor_sync(0xffffffffu, s64, 8);
                s64 += __shfl_xor_sync(0xffffffffu, s64, 4);
                s64 += __shfl_xor_sync(0xffffffffu, s64, 2);
                s64 += __shfl_xor_sync(0xffffffffu, s64, 1);
                if (lane == 0) sBv[64] = MU_DB / s64;
            }
            if (q == 0) sBv[r] = MU_IN / s;
        }
        __syncthreads();
    }

    // ---- Phase E: matching output + score, one fused pass ----
    if (t < NP) { sLa[t] = logf(sAv[t]); sLb[t] = logf(sBv[t]); }
    __syncthreads();

    float* om = out_match + (size_t)b * (NP * NP);
    float p = 0.f;
    for (int i = wid; i < NP; i += 8) {
        float la = sLa[i] + LOG128;
        float ai = sAv[i];
        const float* Ci = C + i * NP;
        const float* Ki = K + i * KP;
        float* omi = om + i * NP;
        for (int j = lane; j < NP; j += 32) {
            float cv = Ci[j];
            omi[j] = cv + la + sLb[j];
            if (write_score && i < 64 && j < 64)
                p += Ki[j] * cv * ai * sBv[j];
        }
    }

    if (write_score) {
        p = warp_sum(p);
        if (lane == 0) sRed[wid] = p;
        __syncthreads();
        if (t == 0) {
            float s = 0.f;
#pragma unroll
            for (int i = 0; i < 8; i++) s += sRed[i];
            out_score[b] = s * 128.0f;
        }
    }
}

extern "C" void kernel_launch(void* const* d_in, const int* in_sizes, int n_in,
                              void* d_out, int out_size) {
    const float* x     = (const float*)d_in[0];
    const float* y     = (const float*)d_in[1];
    const float* gamma = (const float*)d_in[2];
    const float* beta  = (const float*)d_in[3];
    const float* wdb   = (const float*)d_in[4];
    const float* bdb   = (const float*)d_in[5];

    int B = in_sizes[0] / (NN * H);                 // 4096
    size_t msz = (size_t)B * NP * NP;               // matching elements
    float* out_match = (float*)d_out;
    float* out_score = (float*)d_out + msz;
    int write_score = ((size_t)out_size >= msz + (size_t)B) ? 1 : 0;

    sinkhorn_fused_kernel<<<B, 256>>>(x, y, gamma, beta, wdb, bdb,
                                      out_match, out_score, write_score);
}

// round 3
// speedup vs baseline: 1.2221x; 1.2221x over previous
#include <cuda_runtime.h>

// SinkhornScorer fused kernel for GB300 (sm_103a). One CTA per batch element.
// R3: kill the L1TEX bottleneck.
//  - Ownership: warp w owns rows 8w..8w+7; lane l owns cols l and l+32.
//  - GEMM: x-operand loads are warp-uniform (1 wavefront), y conflict-free.
//  - K = exp(C) lives entirely in registers (kreg[8][2]); Sinkhorn row sums
//    via shfl butterfly, col sums via tiny cross-warp smem scratch.
//  - Score computed from register K; C in smem only for the matching output.

namespace {
constexpr int H   = 256;
constexpr int NN  = 64;     // NX == NY
constexpr int NP  = 65;     // with dustbin
constexpr float LOG128 = 4.852030263919617f;   // log(128)
constexpr float MU_IN  = 0.0078125f;           // 1/128
constexpr float MU_DB  = 0.5f;                 // 64/128

__device__ __forceinline__ float warp_sum(float v) {
#pragma unroll
    for (int o = 16; o; o >>= 1) v += __shfl_xor_sync(0xffffffffu, v, o);
    return v;
}
}  // namespace

__global__ void __launch_bounds__(256, 3) sinkhorn_fused_kernel(
    const float* __restrict__ x,      // (B, 64, 256)
    const float* __restrict__ y,      // (B, 64, 256)
    const float* __restrict__ gamma,  // (256,)
    const float* __restrict__ beta,   // (256,)
    const float* __restrict__ wdb,    // (256,1)
    const float* __restrict__ bdb,    // (1,)
    float* __restrict__ out_match,    // (B, 65, 65)
    float* __restrict__ out_score,    // (B,)
    int write_score)
{
    const int b    = blockIdx.x;
    const int t    = threadIdx.x;
    const int lane = t & 31;
    const int wid  = t >> 5;
    const int w8   = wid * 8;
    const int c0   = lane;
    const int c1   = lane + 32;

    // sBuf: GEMM staging (xs 1024 float4 | ys 1024 float4); later overlaid by
    // sC (65*65 = 4225 floats <= 8192).
    __shared__ __align__(16) float sBuf[8192];
    __shared__ __align__(16) float sGw[256];   // gamma*w
    __shared__ float sScale[128];              // 1/||row||, x rows then y rows
    __shared__ float sAlpha[128];              // dustbin alphas
    __shared__ float sBv[NP];                  // b (col scalings)
    __shared__ float sKdbRow[NP];              // K[64][j]
    __shared__ float sKdbCol[NP];              // K[i][64]
    __shared__ float sPart[8 * 66];            // cross-warp col partials
    __shared__ float sAfin[NP], sLa[NP], sLb[NP];
    __shared__ float sRed[16];
    __shared__ float sSgw, sSbw, sA64;

    // ---- constants: gw = gamma*w; S_gw = sum gw; S_bw = sum beta*w + b_db ----
    {
        float gwv = gamma[t] * wdb[t];
        float bwv = beta[t] * wdb[t];
        sGw[t] = gwv;
        gwv = warp_sum(gwv);
        bwv = warp_sum(bwv);
        if (lane == 0) { sRed[wid] = gwv; sRed[8 + wid] = bwv; }
    }
    __syncthreads();
    if (t == 0) {
        float a = 0.f, c = 0.f;
#pragma unroll
        for (int i = 0; i < 8; i++) { a += sRed[i]; c += sRed[8 + i]; }
        sSgw = a;
        sSbw = c + bdb[0];
    }
    __syncthreads();

    const float* xb = x + (size_t)b * NN * H;
    const float* yb = y + (size_t)b * NN * H;

    // ---- Phase A: per-row stats (one warp per row, 16 rows per warp) ----
    {
        const float4* gw4 = (const float4*)sGw;
        for (int rr = wid; rr < 128; rr += 8) {
            const float4* rp4 =
                (const float4*)((rr < 64) ? (xb + rr * H) : (yb + (rr - 64) * H));
            float s1 = 0.f, s2 = 0.f, s3 = 0.f;
#pragma unroll
            for (int qq = 0; qq < 2; qq++) {
                float4 v = rp4[lane + 32 * qq];
                float4 g = gw4[lane + 32 * qq];
                s1 += (v.x + v.y) + (v.z + v.w);
                s2 += v.x * v.x + v.y * v.y + v.z * v.z + v.w * v.w;
                s3 += v.x * g.x + v.y * g.y + v.z * g.z + v.w * g.w;
            }
            s1 = warp_sum(s1);
            s2 = warp_sum(s2);
            s3 = warp_sum(s3);
            if (lane == 0) {
                sScale[rr] = 1.0f / fmaxf(sqrtf(s2), 1e-12f);
                float mu      = s1 * (1.0f / 256.0f);
                float var     = s2 * (1.0f / 256.0f) - mu * mu;
                float inv_std = rsqrtf(var + 1e-5f);
                sAlpha[rr] = tanhf(inv_std * (s3 - mu * sSgw) + sSbw);
            }
        }
    }

    // ---- Phase B: GEMM raw[i][j] = sum_k x[i][k]*y[j][k] ----
    // Thread computes rows w8..w8+7 x cols {c0, c1}: acc[8][2].
    // x loads warp-uniform (cheap); y loads conflict-free via (k4 ^ (row&7)).
    float4* xs4 = (float4*)sBuf;          // [64][16] float4, swizzled
    float4* ys4 = ((float4*)sBuf) + 1024;
    float acc[8][2] = {};
    const float4* xg = (const float4*)xb;   // 64 float4 per row
    const float4* yg = (const float4*)yb;

    for (int kc = 0; kc < 4; kc++) {
        __syncthreads();
#pragma unroll
        for (int qq = 0; qq < 4; qq++) {
            int idx = t + 256 * qq;       // 0..1023
            int row = idx >> 4;
            int c4  = idx & 15;
            int sw  = c4 ^ (row & 7);
            xs4[row * 16 + sw] = xg[row * 64 + kc * 16 + c4];
            ys4[row * 16 + sw] = yg[row * 64 + kc * 16 + c4];
        }
        __syncthreads();
#pragma unroll
        for (int k4 = 0; k4 < 16; k4++) {
            float4 yv0 = ys4[c0 * 16 + (k4 ^ (c0 & 7))];
            float4 yv1 = ys4[c1 * 16 + (k4 ^ (c1 & 7))];
#pragma unroll
            for (int r = 0; r < 8; r++) {
                int row = w8 + r;
                float4 xv = xs4[row * 16 + (k4 ^ (row & 7))];   // warp-uniform
                float a0 = acc[r][0], a1 = acc[r][1];
                a0 = fmaf(xv.x, yv0.x, a0);  a1 = fmaf(xv.x, yv1.x, a1);
                a0 = fmaf(xv.y, yv0.y, a0);  a1 = fmaf(xv.y, yv1.y, a1);
                a0 = fmaf(xv.z, yv0.z, a0);  a1 = fmaf(xv.z, yv1.z, a1);
                a0 = fmaf(xv.w, yv0.w, a0);  a1 = fmaf(xv.w, yv1.w, a1);
                acc[r][0] = a0; acc[r][1] = a1;
            }
        }
    }
    __syncthreads();   // staging reads done; safe to overlay sC

    // ---- Phase C: C = 10*cos into smem; K = exp(C) into registers ----
    float* sC = sBuf;
    float kreg[8][2];
    {
        const float sj0 = sScale[64 + c0] * 10.0f;
        const float sj1 = sScale[64 + c1] * 10.0f;
#pragma unroll
        for (int r = 0; r < 8; r++) {
            float si  = sScale[w8 + r];
            float cv0 = acc[r][0] * si * sj0;
            float cv1 = acc[r][1] * si * sj1;
            sC[(w8 + r) * NP + c0] = cv0;
            sC[(w8 + r) * NP + c1] = cv1;
            kreg[r][0] = __expf(cv0);
            kreg[r][1] = __expf(cv1);
        }
    }
    if (t < 64) {
        float cx = 10.0f * sAlpha[t];          // alpha_x -> dustbin column 64
        sC[t * NP + 64] = cx;  sKdbCol[t] = __expf(cx);
        float cy = 10.0f * sAlpha[64 + t];     // alpha_y -> dustbin row 64
        sC[64 * NP + t] = cy;  sKdbRow[t] = __expf(cy);
    }
    if (t < NP) sBv[t] = 1.0f;                 // v = 0 -> b = 1
    if (t == 0) {
        sC[64 * NP + 64] = -1000.0f;
        sKdbRow[64] = 0.0f;   // K[64][64] = exp(-1000) = 0
        sKdbCol[64] = 0.0f;
        sA64 = 0.0f;
    }
    __syncthreads();

    // ---- Phase D: Sinkhorn, linear domain, K in registers ----
    float a[8];
    float aown = 0.f;
    for (int it = 0; it < 20; it++) {
        // u-phase: row sums of K*b -> a = mu / rowsum
        float b0 = sBv[c0], b1 = sBv[c1], b64 = sBv[64];
        float s[8];
#pragma unroll
        for (int r = 0; r < 8; r++)
            s[r] = fmaf(kreg[r][0], b0, kreg[r][1] * b1);
#pragma unroll
        for (int off = 1; off < 32; off <<= 1) {
#pragma unroll
            for (int r = 0; r < 8; r++)
                s[r] += __shfl_xor_sync(0xffffffffu, s[r], off);
        }
#pragma unroll
        for (int r = 0; r < 8; r++)
            s[r] = fmaf(sKdbCol[w8 + r], b64, s[r]);
        // reciprocal once on lanes 0..7, then broadcast
        float sv = s[0];
#pragma unroll
        for (int r = 1; r < 8; r++) sv = (lane == r) ? s[r] : sv;
        aown = __fdividef(MU_IN, sv);
#pragma unroll
        for (int r = 0; r < 8; r++) a[r] = __shfl_sync(0xffffffffu, aown, r);
        // dustbin row -> a64 (warp 0 only)
        if (wid == 0) {
            float pdb = fmaf(sKdbRow[c0], b0, sKdbRow[c1] * b1);
            pdb = warp_sum(pdb);
            if (lane == 0) sA64 = __fdividef(MU_DB, pdb);
        }
        __syncthreads();
        float a64 = sA64;

        // v-phase: col sums of K^T*a -> b = mu / colsum
        float q0 = 0.f, q1 = 0.f, qdb = 0.f;
#pragma unroll
        for (int r = 0; r < 8; r++) {
            q0  = fmaf(kreg[r][0], a[r], q0);
            q1  = fmaf(kreg[r][1], a[r], q1);
            qdb = fmaf(sKdbCol[w8 + r], a[r], qdb);   // warp-uniform
        }
        sPart[wid * 66 + c0] = q0;
        sPart[wid * 66 + c1] = q1;
        if (lane == 0) sPart[wid * 66 + 64] = qdb;
        __syncthreads();
        if (t < NP) {
            float cs = 0.f;
#pragma unroll
            for (int w = 0; w < 8; w++) cs += sPart[w * 66 + t];
            float bv;
            if (t < 64) bv = __fdividef(MU_IN, fmaf(sKdbRow[t], a64, cs));
            else        bv = __fdividef(MU_DB, cs);
            sBv[t] = bv;
        }
        __syncthreads();
    }

    // ---- Phase E: logs, matching output, score ----
    if (lane < 8) sAfin[w8 + lane] = aown;
    if (t == 0)   sAfin[64] = sA64;
    __syncthreads();
    if (t < NP) { sLa[t] = __logf(sAfin[t]); sLb[t] = __logf(sBv[t]); }
    __syncthreads();

    float* om = out_match + (size_t)b * (NP * NP);
    for (int i = wid; i < NP; i += 8) {
        float la = sLa[i] + LOG128;
        const float* Ci = sC + i * NP;
        float* omi = om + i * NP;
        for (int j = lane; j < NP; j += 32)
            omi[j] = Ci[j] + la + sLb[j];
    }

    if (write_score) {
        // score = 128 * sum_{i,j<64} K_ij * a_i * b_j * C_ij
        float bb0 = sBv[c0], bb1 = sBv[c1];
        float p = 0.f;
#pragma unroll
        for (int r = 0; r < 8; r++) {
            float cv0 = sC[(w8 + r) * NP + c0];
            float cv1 = sC[(w8 + r) * NP + c1];
            p += a[r] * (kreg[r][0] * cv0 * bb0 + kreg[r][1] * cv1 * bb1);
        }
        p = warp_sum(p);
        if (lane == 0) sRed[wid] = p;
        __syncthreads();
        if (t == 0) {
            float ssum = 0.f;
#pragma unroll
            for (int i = 0; i < 8; i++) ssum += sRed[i];
            out_score[b] = ssum * 128.0f;
        }
    }
}

extern "C" void kernel_launch(void* const* d_in, const int* in_sizes, int n_in,
                              void* d_out, int out_size) {
    const float* x     = (const float*)d_in[0];
    const float* y     = (const float*)d_in[1];
    const float* gamma = (const float*)d_in[2];
    const float* beta  = (const float*)d_in[3];
    const float* wdb   = (const float*)d_in[4];
    const float* bdb   = (const float*)d_in[5];

    int B = in_sizes[0] / (NN * H);                 // 4096
    size_t msz = (size_t)B * NP * NP;               // matching elements
    float* out_match = (float*)d_out;
    float* out_score = (float*)d_out + msz;
    int write_score = ((size_t)out_size >= msz + (size_t)B) ? 1 : 0;

    sinkhorn_fused_kernel<<<B, 256>>>(x, y, gamma, beta, wdb, bdb,
                                      out_match, out_score, write_score);
}

// round 4
// speedup vs baseline: 1.3365x; 1.0936x over previous
#include <cuda_runtime.h>

// SinkhornScorer fused kernel for GB300 (sm_103a). One CTA per batch element.
// R4: packed-FP32 (fma.rn.f32x2) GEMM with k-paired accumulators (zero packing
// overhead via ulonglong2 smem loads), 9-shfl multi-value Sinkhorn reduction,
// packed Sinkhorn mat-vecs. L1 and FMA floors both roughly halved.

namespace {
constexpr int H   = 256;
constexpr int NN  = 64;     // NX == NY
constexpr int NP  = 65;     // with dustbin
constexpr float LOG128 = 4.852030263919617f;   // log(128)
constexpr float MU_IN  = 0.0078125f;           // 1/128
constexpr float MU_DB  = 0.5f;                 // 64/128

__device__ __forceinline__ float warp_sum(float v) {
#pragma unroll
    for (int o = 16; o; o >>= 1) v += __shfl_xor_sync(0xffffffffu, v, o);
    return v;
}

__device__ __forceinline__ unsigned long long ffma2(
    unsigned long long a, unsigned long long b, unsigned long long c) {
    unsigned long long d;
    asm("fma.rn.f32x2 %0, %1, %2, %3;" : "=l"(d) : "l"(a), "l"(b), "l"(c));
    return d;
}
__device__ __forceinline__ unsigned long long fmul2(
    unsigned long long a, unsigned long long b) {
    unsigned long long d;
    asm("mul.rn.f32x2 %0, %1, %2;" : "=l"(d) : "l"(a), "l"(b));
    return d;
}
__device__ __forceinline__ unsigned long long pack2(float lo, float hi) {
    unsigned long long d;
    asm("mov.b64 %0, {%1, %2};" : "=l"(d) : "f"(lo), "f"(hi));
    return d;
}
__device__ __forceinline__ void unpack2(unsigned long long v, float& lo, float& hi) {
    asm("mov.b64 {%0, %1}, %2;" : "=f"(lo), "=f"(hi) : "l"(v));
}
__device__ __forceinline__ float pairsum(unsigned long long v) {
    float lo, hi; unpack2(v, lo, hi); return lo + hi;
}
}  // namespace

__global__ void __launch_bounds__(256, 3) sinkhorn_fused_kernel(
    const float* __restrict__ x,      // (B, 64, 256)
    const float* __restrict__ y,      // (B, 64, 256)
    const float* __restrict__ gamma,  // (256,)
    const float* __restrict__ beta,   // (256,)
    const float* __restrict__ wdb,    // (256,1)
    const float* __restrict__ bdb,    // (1,)
    float* __restrict__ out_match,    // (B, 65, 65)
    float* __restrict__ out_score,    // (B,)
    int write_score)
{
    const int b    = blockIdx.x;
    const int t    = threadIdx.x;
    const int lane = t & 31;
    const int wid  = t >> 5;
    const int w8   = wid * 8;
    const int c0   = lane;
    const int c1   = lane + 32;

    __shared__ __align__(16) float sBuf[8192];   // staging; later sC overlay
    __shared__ __align__(16) float sGw[256];
    __shared__ float sScale[128];
    __shared__ float sAlpha[128];
    __shared__ float sBv[NP];
    __shared__ float sKdbRow[NP];                // K[64][j]
    __shared__ float sKdbCol[NP];                // K[i][64]
    __shared__ float sPart[8 * 66];
    __shared__ float sAfin[NP], sLa[NP], sLb[NP];
    __shared__ float sRed[16];
    __shared__ float sSgw, sSbw, sA64;

    // ---- constants ----
    {
        float gwv = gamma[t] * wdb[t];
        float bwv = beta[t] * wdb[t];
        sGw[t] = gwv;
        gwv = warp_sum(gwv);
        bwv = warp_sum(bwv);
        if (lane == 0) { sRed[wid] = gwv; sRed[8 + wid] = bwv; }
    }
    __syncthreads();
    if (t == 0) {
        float a = 0.f, c = 0.f;
#pragma unroll
        for (int i = 0; i < 8; i++) { a += sRed[i]; c += sRed[8 + i]; }
        sSgw = a;
        sSbw = c + bdb[0];
    }
    __syncthreads();

    const float* xb = x + (size_t)b * NN * H;
    const float* yb = y + (size_t)b * NN * H;

    // ---- Phase A: per-row stats ----
    {
        const float4* gw4 = (const float4*)sGw;
        for (int rr = wid; rr < 128; rr += 8) {
            const float4* rp4 =
                (const float4*)((rr < 64) ? (xb + rr * H) : (yb + (rr - 64) * H));
            float s1 = 0.f, s2 = 0.f, s3 = 0.f;
#pragma unroll
            for (int qq = 0; qq < 2; qq++) {
                float4 v = rp4[lane + 32 * qq];
                float4 g = gw4[lane + 32 * qq];
                s1 += (v.x + v.y) + (v.z + v.w);
                s2 += v.x * v.x + v.y * v.y + v.z * v.z + v.w * v.w;
                s3 += v.x * g.x + v.y * g.y + v.z * g.z + v.w * g.w;
            }
            s1 = warp_sum(s1);
            s2 = warp_sum(s2);
            s3 = warp_sum(s3);
            if (lane == 0) {
                sScale[rr] = 1.0f / fmaxf(sqrtf(s2), 1e-12f);
                float mu      = s1 * (1.0f / 256.0f);
                float var     = s2 * (1.0f / 256.0f) - mu * mu;
                float inv_std = rsqrtf(var + 1e-5f);
                sAlpha[rr] = tanhf(inv_std * (s3 - mu * sSgw) + sSbw);
            }
        }
    }

    // ---- Phase B: GEMM with packed f32x2 FMAs (pairs over adjacent k) ----
    float4* xs4 = (float4*)sBuf;            // [64][16] float4, swizzled
    float4* ys4 = ((float4*)sBuf) + 1024;
    const ulonglong2* xs2 = (const ulonglong2*)xs4;
    const ulonglong2* ys2 = (const ulonglong2*)ys4;
    unsigned long long acc2[8][2];
#pragma unroll
    for (int r = 0; r < 8; r++) { acc2[r][0] = 0ull; acc2[r][1] = 0ull; }

    const float4* xg = (const float4*)xb;
    const float4* yg = (const float4*)yb;

    for (int kc = 0; kc < 4; kc++) {
        __syncthreads();
#pragma unroll
        for (int qq = 0; qq < 4; qq++) {
            int idx = t + 256 * qq;       // 0..1023
            int row = idx >> 4;
            int c4  = idx & 15;
            int sw  = c4 ^ (row & 7);
            xs4[row * 16 + sw] = xg[row * 64 + kc * 16 + c4];
            ys4[row * 16 + sw] = yg[row * 64 + kc * 16 + c4];
        }
        __syncthreads();
#pragma unroll
        for (int k4 = 0; k4 < 16; k4++) {
            ulonglong2 yv0 = ys2[c0 * 16 + (k4 ^ (c0 & 7))];
            ulonglong2 yv1 = ys2[c1 * 16 + (k4 ^ (c1 & 7))];
#pragma unroll
            for (int r = 0; r < 8; r++) {
                int row = w8 + r;
                ulonglong2 xv = xs2[row * 16 + (k4 ^ (row & 7))];  // warp-uniform
                acc2[r][0] = ffma2(xv.x, yv0.x, acc2[r][0]);
                acc2[r][0] = ffma2(xv.y, yv0.y, acc2[r][0]);
                acc2[r][1] = ffma2(xv.x, yv1.x, acc2[r][1]);
                acc2[r][1] = ffma2(xv.y, yv1.y, acc2[r][1]);
            }
        }
    }
    __syncthreads();   // staging reads done; safe to overlay sC

    // ---- Phase C: C into smem; K = exp(C) packed in registers ----
    float* sC = sBuf;
    unsigned long long kreg2[8];    // {K[r][c0], K[r][c1]}
    {
        const float sj0 = sScale[64 + c0] * 10.0f;
        const float sj1 = sScale[64 + c1] * 10.0f;
#pragma unroll
        for (int r = 0; r < 8; r++) {
            float si  = sScale[w8 + r];
            float cv0 = pairsum(acc2[r][0]) * si * sj0;
            float cv1 = pairsum(acc2[r][1]) * si * sj1;
            sC[(w8 + r) * NP + c0] = cv0;
            sC[(w8 + r) * NP + c1] = cv1;
            kreg2[r] = pack2(__expf(cv0), __expf(cv1));
        }
    }
    if (t < 64) {
        float cx = 10.0f * sAlpha[t];          // alpha_x -> dustbin column 64
        sC[t * NP + 64] = cx;  sKdbCol[t] = __expf(cx);
        float cy = 10.0f * sAlpha[64 + t];     // alpha_y -> dustbin row 64
        sC[64 * NP + t] = cy;  sKdbRow[t] = __expf(cy);
    }
    if (t < NP) sBv[t] = 1.0f;
    if (t == 0) {
        sC[64 * NP + 64] = -1000.0f;
        sKdbRow[64] = 0.0f;
        sKdbCol[64] = 0.0f;
        sA64 = 0.0f;
    }
    __syncthreads();

    // ---- Phase D: Sinkhorn, linear domain ----
    const bool b4 = (lane & 16) != 0;
    const bool b3 = (lane & 8)  != 0;
    const bool bq = (lane & 4)  != 0;
    const int  rl = (lane >> 2) & 7;     // row this lane ends up owning
    float a[8];
    float rcp = 0.f;
    for (int it = 0; it < 20; it++) {
        // u-phase: row sums of K*b
        float bv0 = sBv[c0], bv1 = sBv[c1], b64 = sBv[64];
        unsigned long long b2p = pack2(bv0, bv1);
        float s[8];
#pragma unroll
        for (int r = 0; r < 8; r++) s[r] = pairsum(fmul2(kreg2[r], b2p));
        // multi-value collapse: offsets 16, 8, 4 fold 8 regs -> 1
        float u0, u1, u2, u3;
        {
            float t0, t1, t2, t3;
            t0 = __shfl_xor_sync(0xffffffffu, b4 ? s[0] : s[4], 16);
            t1 = __shfl_xor_sync(0xffffffffu, b4 ? s[1] : s[5], 16);
            t2 = __shfl_xor_sync(0xffffffffu, b4 ? s[2] : s[6], 16);
            t3 = __shfl_xor_sync(0xffffffffu, b4 ? s[3] : s[7], 16);
            u0 = (b4 ? s[4] : s[0]) + t0;
            u1 = (b4 ? s[5] : s[1]) + t1;
            u2 = (b4 ? s[6] : s[2]) + t2;
            u3 = (b4 ? s[7] : s[3]) + t3;
        }
        float w0, w1;
        {
            float t0 = __shfl_xor_sync(0xffffffffu, b3 ? u0 : u2, 8);
            float t1 = __shfl_xor_sync(0xffffffffu, b3 ? u1 : u3, 8);
            w0 = (b3 ? u2 : u0) + t0;
            w1 = (b3 ? u3 : u1) + t1;
        }
        float z;
        {
            float t0 = __shfl_xor_sync(0xffffffffu, bq ? w0 : w1, 4);
            z = (bq ? w1 : w0) + t0;
        }
        z += __shfl_xor_sync(0xffffffffu, z, 2);
        z += __shfl_xor_sync(0xffffffffu, z, 1);
        z = fmaf(sKdbCol[w8 + rl], b64, z);      // dustbin col, once per lane
        rcp = __fdividef(MU_IN, z);              // a for row w8+rl
#pragma unroll
        for (int r = 0; r < 8; r++) a[r] = __shfl_sync(0xffffffffu, rcp, r * 4);
        // dustbin row -> a64 (warp 0)
        if (wid == 0) {
            float pdb = fmaf(sKdbRow[c0], bv0, sKdbRow[c1] * bv1);
            pdb = warp_sum(pdb);
            if (lane == 0) sA64 = __fdividef(MU_DB, pdb);
        }
        __syncthreads();
        float a64 = sA64;

        // v-phase: col sums of K^T*a
        unsigned long long q2 = 0ull;
        float qdb = 0.f;
#pragma unroll
        for (int r = 0; r < 8; r++) {
            q2  = ffma2(kreg2[r], pack2(a[r], a[r]), q2);
            qdb = fmaf(sKdbCol[w8 + r], a[r], qdb);
        }
        float q0, q1;
        unpack2(q2, q0, q1);
        sPart[wid * 66 + c0] = q0;
        sPart[wid * 66 + c1] = q1;
        if (lane == 0) sPart[wid * 66 + 64] = qdb;
        __syncthreads();
        if (t < NP) {
            float cs = 0.f;
#pragma unroll
            for (int w = 0; w < 8; w++) cs += sPart[w * 66 + t];
            float bv;
            if (t < 64) bv = __fdividef(MU_IN, fmaf(sKdbRow[t], a64, cs));
            else        bv = __fdividef(MU_DB, cs);
            sBv[t] = bv;
        }
        __syncthreads();
    }

    // ---- Phase E: logs, matching output, score ----
    if ((lane & 3) == 0) sAfin[w8 + rl] = rcp;
    if (t == 0)          sAfin[64] = sA64;
    __syncthreads();
    if (t < NP) { sLa[t] = __logf(sAfin[t]); sLb[t] = __logf(sBv[t]); }
    __syncthreads();

    float* om = out_match + (size_t)b * (NP * NP);
    for (int i = wid; i < NP; i += 8) {
        float la = sLa[i] + LOG128;
        const float* Ci = sC + i * NP;
        float* omi = om + i * NP;
        for (int j = lane; j < NP; j += 32)
            omi[j] = Ci[j] + la + sLb[j];
    }

    if (write_score) {
        float bb0 = sBv[c0], bb1 = sBv[c1];
        float p = 0.f;
#pragma unroll
        for (int r = 0; r < 8; r++) {
            float k0, k1;
            unpack2(kreg2[r], k0, k1);
            float cv0 = sC[(w8 + r) * NP + c0];
            float cv1 = sC[(w8 + r) * NP + c1];
            p += a[r] * (k0 * cv0 * bb0 + k1 * cv1 * bb1);
        }
        p = warp_sum(p);
        if (lane == 0) sRed[wid] = p;
        __syncthreads();
        if (t == 0) {
            float ssum = 0.f;
#pragma unroll
            for (int i = 0; i < 8; i++) ssum += sRed[i];
            out_score[b] = ssum * 128.0f;
        }
    }
}

extern "C" void kernel_launch(void* const* d_in, const int* in_sizes, int n_in,
                              void* d_out, int out_size) {
    const float* x     = (const float*)d_in[0];
    const float* y     = (const float*)d_in[1];
    const float* gamma = (const float*)d_in[2];
    const float* beta  = (const float*)d_in[3];
    const float* wdb   = (const float*)d_in[4];
    const float* bdb   = (const float*)d_in[5];

    int B = in_sizes[0] / (NN * H);                 // 4096
    size_t msz = (size_t)B * NP * NP;               // matching elements
    float* out_match = (float*)d_out;
    float* out_score = (float*)d_out + msz;
    int write_score = ((size_t)out_size >= msz + (size_t)B) ? 1 : 0;

    sinkhorn_fused_kernel<<<B, 256>>>(x, y, gamma, beta, wdb, bdb,
                                      out_match, out_score, write_score);
}